// round 2
// baseline (speedup 1.0000x reference)
#include <cuda_runtime.h>

#define NB 8
#define CC 256
#define NN 4096
#define DD 32

// Scratch (device globals: allocation-free per harness rules)
__device__ float g_q[(size_t)NB * NN * DD];   // [b][n][32]
__device__ float g_k[(size_t)NB * NN * DD];   // [b][m][32]
__device__ float g_v[(size_t)NB * NN * CC];   // [b][m][256]

// ---------------------------------------------------------------------------
// Projection GEMM: out[b][n][r] = sum_c W[r][c] * x[b][c][n] + bias[r]
// Tile: 32 r x 128 n per block, 256 threads, each thread 4r x 4n.
// ---------------------------------------------------------------------------
__global__ void __launch_bounds__(256) proj_kernel(
    const float* __restrict__ W, const float* __restrict__ bias,
    const float* __restrict__ x, float* __restrict__ out, int R)
{
    __shared__ float xs[32][128];
    __shared__ float ws[32][33];   // pad to kill bank conflicts on column reads

    const int tid = threadIdx.x;
    const int b  = blockIdx.y;
    const int n0 = blockIdx.x * 128;
    const int r0 = blockIdx.z * 32;
    const int tr = tid & 7;    // r-group (4 rows each)
    const int tn = tid >> 3;   // n-group (4 cols each)

    float acc[4][4];
#pragma unroll
    for (int i = 0; i < 4; i++) {
        float bb = bias[r0 + tr * 4 + i];
#pragma unroll
        for (int j = 0; j < 4; j++) acc[i][j] = bb;
    }

    for (int c0 = 0; c0 < CC; c0 += 32) {
#pragma unroll
        for (int k = 0; k < 16; k++) {
            int idx = tid + k * 256;
            int row = idx >> 7, col = idx & 127;
            xs[row][col] = x[((size_t)b * CC + (c0 + row)) * NN + n0 + col];
        }
#pragma unroll
        for (int k = 0; k < 4; k++) {
            int idx = tid + k * 256;
            int row = idx >> 5, col = idx & 31;
            ws[row][col] = W[(size_t)(r0 + row) * CC + c0 + col];
        }
        __syncthreads();

#pragma unroll 8
        for (int cc = 0; cc < 32; cc++) {
            float4 xv = *(const float4*)&xs[cc][tn * 4];
            float wr[4];
#pragma unroll
            for (int i = 0; i < 4; i++) wr[i] = ws[tr * 4 + i][cc];
#pragma unroll
            for (int i = 0; i < 4; i++) {
                acc[i][0] += wr[i] * xv.x;
                acc[i][1] += wr[i] * xv.y;
                acc[i][2] += wr[i] * xv.z;
                acc[i][3] += wr[i] * xv.w;
            }
        }
        __syncthreads();
    }

#pragma unroll
    for (int j = 0; j < 4; j++) {
        int n = n0 + tn * 4 + j;
        float4 v = make_float4(acc[0][j], acc[1][j], acc[2][j], acc[3][j]);
        *(float4*)&out[((size_t)b * NN + n) * R + r0 + tr * 4] = v;
    }
}

// ---------------------------------------------------------------------------
// Fused flash attention + epilogue.
// Grid: (N/64, B). Block: 256 threads (8 warps).
// Warp w owns queries n0 + w*8 .. +7. Lane l owns channels {j*128 + l*4 + jj}.
// smem: Qs[64][32] | Ks[64][33] | Ps[64][65] | Vs[64][260]  (~100 KB dynamic)
// ---------------------------------------------------------------------------
#define KSTR 33
#define PSTR 65
#define VSTR 260

extern __shared__ float fsm[];

__global__ void __launch_bounds__(256) flash_kernel(
    const float* __restrict__ x, const float* __restrict__ gamma,
    float* __restrict__ out)
{
    float* Qs = fsm;                   // 64*32
    float* Ks = Qs + 64 * 32;          // 64*33
    float* Ps = Ks + 64 * KSTR;        // 64*65
    float* Vs = Ps + 64 * PSTR;        // 64*260

    const int tid = threadIdx.x;
    const int w = tid >> 5;
    const int l = tid & 31;
    const int b  = blockIdx.y;
    const int n0 = blockIdx.x * 64;

    // Load Q tile (contiguous 64x32)
#pragma unroll
    for (int k = 0; k < 8; k++) {
        int idx = tid + k * 256;
        Qs[idx] = g_q[((size_t)b * NN + n0) * DD + idx];
    }

    float mi[8], li[8];
    float acc[8][8];
#pragma unroll
    for (int i = 0; i < 8; i++) {
        mi[i] = -1e30f; li[i] = 0.f;
#pragma unroll
        for (int j = 0; j < 8; j++) acc[i][j] = 0.f;
    }

    for (int m0 = 0; m0 < NN; m0 += 64) {
        // K tile 64x32 -> Ks (stride 33)
#pragma unroll
        for (int k = 0; k < 8; k++) {
            int idx = tid + k * 256;
            int row = idx >> 5, d = idx & 31;
            Ks[row * KSTR + d] = g_k[((size_t)b * NN + m0) * DD + idx];
        }
        // V tile 64x256 -> Vs (stride 260), float4
#pragma unroll
        for (int k = 0; k < 16; k++) {
            int idx4 = tid + k * 256;            // 0..4095 float4 units
            int m = idx4 >> 6, c4 = idx4 & 63;
            float4 vv = *(const float4*)&g_v[((size_t)b * NN + m0 + m) * CC + c4 * 4];
            *(float4*)&Vs[m * VSTR + c4 * 4] = vv;
        }
        __syncthreads();

        // ---- S = Q K^T (lane l owns keys m=l and m=l+32) ----
        float s0[8], s1[8];
#pragma unroll
        for (int i = 0; i < 8; i++) { s0[i] = 0.f; s1[i] = 0.f; }
#pragma unroll 8
        for (int d = 0; d < 32; d++) {
            float k0 = Ks[l * KSTR + d];
            float k1 = Ks[(l + 32) * KSTR + d];
#pragma unroll
            for (int i = 0; i < 8; i++) {
                float qv = Qs[(w * 8 + i) * 32 + d];   // broadcast
                s0[i] += qv * k0;
                s1[i] += qv * k1;
            }
        }

        // ---- online softmax, write P ----
#pragma unroll
        for (int i = 0; i < 8; i++) {
            float sm = fmaxf(s0[i], s1[i]);
#pragma unroll
            for (int off = 16; off; off >>= 1)
                sm = fmaxf(sm, __shfl_xor_sync(0xffffffffu, sm, off));
            float mnew = fmaxf(mi[i], sm);
            float corr = __expf(mi[i] - mnew);
            float p0 = __expf(s0[i] - mnew);
            float p1 = __expf(s1[i] - mnew);
            float ps = p0 + p1;
#pragma unroll
            for (int off = 16; off; off >>= 1)
                ps += __shfl_xor_sync(0xffffffffu, ps, off);
            li[i] = li[i] * corr + ps;
            mi[i] = mnew;
#pragma unroll
            for (int j = 0; j < 8; j++) acc[i][j] *= corr;
            Ps[(w * 8 + i) * PSTR + l]      = p0;
            Ps[(w * 8 + i) * PSTR + l + 32] = p1;
        }
        __syncthreads();

        // ---- O += P V ----
#pragma unroll 2
        for (int m = 0; m < 64; m++) {
            float4 v0 = *(const float4*)&Vs[m * VSTR + l * 4];
            float4 v1 = *(const float4*)&Vs[m * VSTR + 128 + l * 4];
#pragma unroll
            for (int i = 0; i < 8; i++) {
                float p = Ps[(w * 8 + i) * PSTR + m];   // broadcast
                acc[i][0] += p * v0.x; acc[i][1] += p * v0.y;
                acc[i][2] += p * v0.z; acc[i][3] += p * v0.w;
                acc[i][4] += p * v1.x; acc[i][5] += p * v1.y;
                acc[i][6] += p * v1.z; acc[i][7] += p * v1.w;
            }
        }
        __syncthreads();
    }

    // ---- epilogue: out = gamma * (O / l) + x ----
    const float g = gamma[0];
#pragma unroll
    for (int i = 0; i < 8; i++) {
        int n = n0 + w * 8 + i;
        float inv = 1.0f / li[i];
#pragma unroll
        for (int j = 0; j < 8; j++) {
            int c = (j >> 2) * 128 + l * 4 + (j & 3);
            size_t idx = ((size_t)b * CC + c) * NN + n;
            out[idx] = g * (acc[i][j] * inv) + x[idx];
        }
    }
}

// ---------------------------------------------------------------------------
extern "C" void kernel_launch(void* const* d_in, const int* in_sizes, int n_in,
                              void* d_out, int out_size)
{
    const float* x     = (const float*)d_in[0];
    const float* wq    = (const float*)d_in[1];
    const float* bq    = (const float*)d_in[2];
    const float* wk    = (const float*)d_in[3];
    const float* bk    = (const float*)d_in[4];
    const float* wv    = (const float*)d_in[5];
    const float* bv    = (const float*)d_in[6];
    const float* gamma = (const float*)d_in[7];
    float* out = (float*)d_out;

    float *qp, *kp, *vp;
    cudaGetSymbolAddress((void**)&qp, g_q);
    cudaGetSymbolAddress((void**)&kp, g_k);
    cudaGetSymbolAddress((void**)&vp, g_v);

    dim3 blk(256);
    proj_kernel<<<dim3(NN / 128, NB, 1), blk>>>(wq, bq, x, qp, DD);
    proj_kernel<<<dim3(NN / 128, NB, 1), blk>>>(wk, bk, x, kp, DD);
    proj_kernel<<<dim3(NN / 128, NB, 8), blk>>>(wv, bv, x, vp, CC);

    const size_t SMEM = (size_t)(64 * 32 + 64 * KSTR + 64 * PSTR + 64 * VSTR) * sizeof(float);
    cudaFuncSetAttribute(flash_kernel,
                         cudaFuncAttributeMaxDynamicSharedMemorySize, (int)SMEM);
    flash_kernel<<<dim3(NN / 64, NB), blk, SMEM>>>(x, gamma, out);
}

// round 4
// speedup vs baseline: 2.1878x; 2.1878x over previous
#include <cuda_runtime.h>
#include <cuda_bf16.h>
#include <cstdint>

#define NB 8
#define CC 256
#define NN 4096
#define DD 32
#define BQ 64
#define BK 64
#define NT (NN / BK)

// Pre-split bf16 operands (hi + lo ~ fp32-grade with 3-term products)
__device__ __align__(128) __nv_bfloat16 g_qh[(size_t)NB * NN * DD];
__device__ __align__(128) __nv_bfloat16 g_ql[(size_t)NB * NN * DD];
__device__ __align__(128) __nv_bfloat16 g_kh[(size_t)NB * NN * DD];
__device__ __align__(128) __nv_bfloat16 g_kl[(size_t)NB * NN * DD];
__device__ __align__(128) __nv_bfloat16 g_vh[(size_t)NB * CC * NN];  // [b][c][n]
__device__ __align__(128) __nv_bfloat16 g_vl[(size_t)NB * CC * NN];

// ---- smem byte offsets (dynamic smem) ----
#define QSTR 80                    // 32 bf16 row padded to 20 words (stride%32w==20)
#define VSTR 144                   // 64 bf16 row padded to 36 words (36%32==4)
#define OSTR 260                   // stage stride in floats
#define QH_OFF 0
#define QL_OFF 5120
#define K_OFF(buf, mat) (10240 + (buf) * 10240 + (mat) * 5120)
#define V_OFF(buf, mat) (30720 + (buf) * 73728 + (mat) * 36864)
#define STAGE_OFF 30720            // reuses V buf0 at epilogue (64*260*4 = 66560 B)
#define SMEM_BYTES 178176

// ---- helpers ----
__device__ __forceinline__ uint32_t smem_u32(const void* p) {
    uint32_t a;
    asm("{ .reg .u64 t; cvta.to.shared.u64 t, %1; cvt.u32.u64 %0, t; }" : "=r"(a) : "l"(p));
    return a;
}
__device__ __forceinline__ void cpa16(uint32_t dst, const void* src) {
    asm volatile("cp.async.cg.shared.global [%0], [%1], 16;" :: "r"(dst), "l"(src) : "memory");
}
__device__ __forceinline__ void cp_commit() { asm volatile("cp.async.commit_group;" ::: "memory"); }
template <int N> __device__ __forceinline__ void cp_wait() {
    asm volatile("cp.async.wait_group %0;" :: "n"(N) : "memory");
}
__device__ __forceinline__ void mma_bf16(float* d, const uint32_t* a, const uint32_t* b) {
    asm volatile(
        "mma.sync.aligned.m16n8k16.row.col.f32.bf16.bf16.f32 "
        "{%0,%1,%2,%3}, {%4,%5,%6,%7}, {%8,%9}, {%0,%1,%2,%3};"
        : "+f"(d[0]), "+f"(d[1]), "+f"(d[2]), "+f"(d[3])
        : "r"(a[0]), "r"(a[1]), "r"(a[2]), "r"(a[3]), "r"(b[0]), "r"(b[1]));
}
__device__ __forceinline__ uint32_t packbf(__nv_bfloat16 lo, __nv_bfloat16 hi) {
    __nv_bfloat162 t; t.x = lo; t.y = hi;
    return *(uint32_t*)&t;
}

// per-thread share of one K/V tile load (18 cp.async of 16B)
__device__ __forceinline__ void load_kv(char* smp, int b, int m0, int buf, int tid) {
#pragma unroll
    for (int it = 0; it < 2; it++) {            // K: 64 rows x 4 chunks x 2 mats
        int idx = tid + it * 256;
        int mat = idx >> 8, r = (idx >> 2) & 63, j = idx & 3;
        const __nv_bfloat16* src = (mat ? g_kl : g_kh) +
            ((size_t)(b * NN + m0 + r)) * DD + j * 8;
        cpa16(smem_u32(smp + K_OFF(buf, mat) + r * QSTR + j * 16), src);
    }
#pragma unroll
    for (int it = 0; it < 16; it++) {           // V: 256 rows x 8 chunks x 2 mats
        int idx = tid + it * 256;
        int mat = idx >> 11, r = (idx >> 3) & 255, j = idx & 7;
        const __nv_bfloat16* src = (mat ? g_vl : g_vh) +
            ((size_t)(b * CC + r)) * NN + m0 + j * 8;
        cpa16(smem_u32(smp + V_OFF(buf, mat) + r * VSTR + j * 16), src);
    }
}

// ---------------------------------------------------------------------------
// Projection: q/k -> [b][n][32] bf16 hi/lo
// ---------------------------------------------------------------------------
__global__ void __launch_bounds__(256) proj_qk(
    const float* __restrict__ W, const float* __restrict__ bias,
    const float* __restrict__ x,
    __nv_bfloat16* __restrict__ oh, __nv_bfloat16* __restrict__ ol)
{
    __shared__ float xs[32][128];
    __shared__ float ws[32][33];
    const int tid = threadIdx.x;
    const int b  = blockIdx.y;
    const int n0 = blockIdx.x * 128;
    const int tr = tid & 7, tn = tid >> 3;

    float acc[4][4];
#pragma unroll
    for (int i = 0; i < 4; i++) {
        float bb = bias[tr * 4 + i];
#pragma unroll
        for (int j = 0; j < 4; j++) acc[i][j] = bb;
    }
    for (int c0 = 0; c0 < CC; c0 += 32) {
#pragma unroll
        for (int k = 0; k < 16; k++) {
            int idx = tid + k * 256;
            int row = idx >> 7, col = idx & 127;
            xs[row][col] = x[((size_t)b * CC + (c0 + row)) * NN + n0 + col];
        }
#pragma unroll
        for (int k = 0; k < 4; k++) {
            int idx = tid + k * 256;
            int row = idx >> 5, col = idx & 31;
            ws[row][col] = W[(size_t)row * CC + c0 + col];
        }
        __syncthreads();
#pragma unroll 8
        for (int cc = 0; cc < 32; cc++) {
            float4 xv = *(const float4*)&xs[cc][tn * 4];
            float wr[4];
#pragma unroll
            for (int i = 0; i < 4; i++) wr[i] = ws[tr * 4 + i][cc];
#pragma unroll
            for (int i = 0; i < 4; i++) {
                acc[i][0] += wr[i] * xv.x; acc[i][1] += wr[i] * xv.y;
                acc[i][2] += wr[i] * xv.z; acc[i][3] += wr[i] * xv.w;
            }
        }
        __syncthreads();
    }
#pragma unroll
    for (int j = 0; j < 4; j++) {
        int n = n0 + tn * 4 + j;
#pragma unroll
        for (int i = 0; i < 4; i++) {
            int r = tr * 4 + i;
            float a = acc[i][j];
            __nv_bfloat16 h = __float2bfloat16(a);
            oh[((size_t)(b * NN + n)) * DD + r] = h;
            ol[((size_t)(b * NN + n)) * DD + r] = __float2bfloat16(a - __bfloat162float(h));
        }
    }
}

// ---------------------------------------------------------------------------
// Projection: v -> [b][c][n] bf16 hi/lo
// ---------------------------------------------------------------------------
__global__ void __launch_bounds__(256) proj_v(
    const float* __restrict__ W, const float* __restrict__ bias,
    const float* __restrict__ x,
    __nv_bfloat16* __restrict__ oh, __nv_bfloat16* __restrict__ ol)
{
    __shared__ float xs[32][128];
    __shared__ float ws[32][33];
    const int tid = threadIdx.x;
    const int b  = blockIdx.y;
    const int n0 = blockIdx.x * 128;
    const int r0 = blockIdx.z * 32;
    const int tr = tid & 7, tn = tid >> 3;

    float acc[4][4];
#pragma unroll
    for (int i = 0; i < 4; i++) {
        float bb = bias[r0 + tr * 4 + i];
#pragma unroll
        for (int j = 0; j < 4; j++) acc[i][j] = bb;
    }
    for (int c0 = 0; c0 < CC; c0 += 32) {
#pragma unroll
        for (int k = 0; k < 16; k++) {
            int idx = tid + k * 256;
            int row = idx >> 7, col = idx & 127;
            xs[row][col] = x[((size_t)b * CC + (c0 + row)) * NN + n0 + col];
        }
#pragma unroll
        for (int k = 0; k < 4; k++) {
            int idx = tid + k * 256;
            int row = idx >> 5, col = idx & 31;
            ws[row][col] = W[(size_t)(r0 + row) * CC + c0 + col];
        }
        __syncthreads();
#pragma unroll 8
        for (int cc = 0; cc < 32; cc++) {
            float4 xv = *(const float4*)&xs[cc][tn * 4];
            float wr[4];
#pragma unroll
            for (int i = 0; i < 4; i++) wr[i] = ws[tr * 4 + i][cc];
#pragma unroll
            for (int i = 0; i < 4; i++) {
                acc[i][0] += wr[i] * xv.x; acc[i][1] += wr[i] * xv.y;
                acc[i][2] += wr[i] * xv.z; acc[i][3] += wr[i] * xv.w;
            }
        }
        __syncthreads();
    }
#pragma unroll
    for (int i = 0; i < 4; i++) {
        int r = r0 + tr * 4 + i;
#pragma unroll
        for (int j = 0; j < 4; j++) {
            int n = n0 + tn * 4 + j;
            float a = acc[i][j];
            __nv_bfloat16 h = __float2bfloat16(a);
            oh[((size_t)(b * CC + r)) * NN + n] = h;
            ol[((size_t)(b * CC + r)) * NN + n] = __float2bfloat16(a - __bfloat162float(h));
        }
    }
}

// ---------------------------------------------------------------------------
// Flash attention via mma.sync (HMMA bf16, 3-term hi/lo), unnormalized exp.
// Grid (NN/BQ, NB) = (64, 8); 256 threads = 8 warps in (4 q-rows x 2 c-halves).
// ---------------------------------------------------------------------------
__global__ void __launch_bounds__(256, 1) flash_mma(
    const float* __restrict__ x, const float* __restrict__ gamma,
    float* __restrict__ out)
{
    extern __shared__ char smp[];
    const int tid  = threadIdx.x;
    const int wid  = tid >> 5;
    const int lane = tid & 31;
    const int wr   = wid >> 1;        // 0..3: q-rows  wr*16..+15
    const int wc   = wid & 1;         // 0..1: channels wc*128..+127
    const int g    = lane >> 2;       // groupID
    const int tg   = lane & 3;        // threadID-in-group
    const int b  = blockIdx.y;
    const int q0 = blockIdx.x * BQ;

    // ---- prologue: Q + tile-0 K/V ----
#pragma unroll
    for (int it = 0; it < 2; it++) {       // Q: 64 rows x 4 chunks x 2 mats
        int idx = tid + it * 256;
        int mat = idx >> 8, r = (idx >> 2) & 63, j = idx & 3;
        const __nv_bfloat16* src = (mat ? g_ql : g_qh) +
            ((size_t)(b * NN + q0 + r)) * DD + j * 8;
        cpa16(smem_u32(smp + (mat ? QL_OFF : QH_OFF) + r * QSTR + j * 16), src);
    }
    load_kv(smp, b, 0, 0, tid);
    cp_commit();
    cp_wait<0>();
    __syncthreads();

    // ---- preload Q fragments (constant across tiles) ----
    uint32_t QhA[2][4], QlA[2][4];
    {
        int rowA = wr * 16 + g, rowB = rowA + 8;
#pragma unroll
        for (int kf = 0; kf < 2; kf++) {
            int w0 = (kf * 8 + tg) * 4;
            QhA[kf][0] = *(const uint32_t*)(smp + QH_OFF + rowA * QSTR + w0);
            QhA[kf][1] = *(const uint32_t*)(smp + QH_OFF + rowB * QSTR + w0);
            QhA[kf][2] = *(const uint32_t*)(smp + QH_OFF + rowA * QSTR + w0 + 16);
            QhA[kf][3] = *(const uint32_t*)(smp + QH_OFF + rowB * QSTR + w0 + 16);
            QlA[kf][0] = *(const uint32_t*)(smp + QL_OFF + rowA * QSTR + w0);
            QlA[kf][1] = *(const uint32_t*)(smp + QL_OFF + rowB * QSTR + w0);
            QlA[kf][2] = *(const uint32_t*)(smp + QL_OFF + rowA * QSTR + w0 + 16);
            QlA[kf][3] = *(const uint32_t*)(smp + QL_OFF + rowB * QSTR + w0 + 16);
        }
    }

    float O[16][4];
#pragma unroll
    for (int i = 0; i < 16; i++)
#pragma unroll
        for (int j = 0; j < 4; j++) O[i][j] = 0.f;
    float lsumA = 0.f, lsumB = 0.f;
    uint32_t Ph[8][2], Pl[8][2];

    for (int t = 0; t < NT; t++) {
        const int buf = t & 1;
        if (t) cp_wait<0>();
        __syncthreads();
        if (t + 1 < NT) { load_kv(smp, b, (t + 1) * BK, buf ^ 1, tid); cp_commit(); }

        // ---- S = Q K^T (both wc warps duplicate; cheap) + exp + pack ----
        const char* kh = smp + K_OFF(buf, 0);
        const char* kl = smp + K_OFF(buf, 1);
#pragma unroll
        for (int nt = 0; nt < 8; nt++) {
            int krow = nt * 8 + g;
            uint32_t KhB[2][2], KlB[2][2];
#pragma unroll
            for (int kf = 0; kf < 2; kf++) {
                int w0 = (kf * 8 + tg) * 4;
                KhB[kf][0] = *(const uint32_t*)(kh + krow * QSTR + w0);
                KhB[kf][1] = *(const uint32_t*)(kh + krow * QSTR + w0 + 16);
                KlB[kf][0] = *(const uint32_t*)(kl + krow * QSTR + w0);
                KlB[kf][1] = *(const uint32_t*)(kl + krow * QSTR + w0 + 16);
            }
            float S[4] = {0.f, 0.f, 0.f, 0.f};
            mma_bf16(S, QhA[0], KhB[0]); mma_bf16(S, QhA[1], KhB[1]);
            mma_bf16(S, QlA[0], KhB[0]); mma_bf16(S, QlA[1], KhB[1]);
            mma_bf16(S, QhA[0], KlB[0]); mma_bf16(S, QhA[1], KlB[1]);

            float p0 = __expf(S[0]), p1 = __expf(S[1]);
            float p2 = __expf(S[2]), p3 = __expf(S[3]);
            lsumA += p0 + p1;
            lsumB += p2 + p3;
            __nv_bfloat16 h0 = __float2bfloat16(p0), h1 = __float2bfloat16(p1);
            __nv_bfloat16 h2 = __float2bfloat16(p2), h3 = __float2bfloat16(p3);
            Ph[nt][0] = packbf(h0, h1);
            Ph[nt][1] = packbf(h2, h3);
            Pl[nt][0] = packbf(__float2bfloat16(p0 - __bfloat162float(h0)),
                               __float2bfloat16(p1 - __bfloat162float(h1)));
            Pl[nt][1] = packbf(__float2bfloat16(p2 - __bfloat162float(h2)),
                               __float2bfloat16(p3 - __bfloat162float(h3)));
        }

        // ---- O += P V^T (P stays in registers) ----
        const char* vh = smp + V_OFF(buf, 0);
        const char* vl = smp + V_OFF(buf, 1);
#pragma unroll
        for (int nt = 0; nt < 16; nt++) {
            int crow = wc * 128 + nt * 8 + g;
            uint32_t VhB[4][2], VlB[4][2];
#pragma unroll
            for (int kf = 0; kf < 4; kf++) {
                int w0 = (kf * 8 + tg) * 4;
                VhB[kf][0] = *(const uint32_t*)(vh + crow * VSTR + w0);
                VhB[kf][1] = *(const uint32_t*)(vh + crow * VSTR + w0 + 16);
                VlB[kf][0] = *(const uint32_t*)(vl + crow * VSTR + w0);
                VlB[kf][1] = *(const uint32_t*)(vl + crow * VSTR + w0 + 16);
            }
#pragma unroll
            for (int kf = 0; kf < 4; kf++) {
                uint32_t Ah[4] = {Ph[2*kf][0], Ph[2*kf][1], Ph[2*kf+1][0], Ph[2*kf+1][1]};
                uint32_t Al[4] = {Pl[2*kf][0], Pl[2*kf][1], Pl[2*kf+1][0], Pl[2*kf+1][1]};
                mma_bf16(O[nt], Ah, VhB[kf]);
                mma_bf16(O[nt], Al, VhB[kf]);
                mma_bf16(O[nt], Ah, VlB[kf]);
            }
        }
    }

    // ---- normalize + epilogue ----
    lsumA += __shfl_xor_sync(0xffffffffu, lsumA, 1);
    lsumA += __shfl_xor_sync(0xffffffffu, lsumA, 2);
    lsumB += __shfl_xor_sync(0xffffffffu, lsumB, 1);
    lsumB += __shfl_xor_sync(0xffffffffu, lsumB, 2);
    const float gm = gamma[0];
    const float scA = gm / lsumA;
    const float scB = gm / lsumB;

    __syncthreads();
    float* stage = (float*)(smp + STAGE_OFF);   // [q=64][c=256], stride OSTR
    {
        int q = wr * 16 + g;
#pragma unroll
        for (int nt = 0; nt < 16; nt++) {
            int c = wc * 128 + nt * 8 + tg * 2;
            stage[q * OSTR + c]           = O[nt][0] * scA;
            stage[q * OSTR + c + 1]       = O[nt][1] * scA;
            stage[(q + 8) * OSTR + c]     = O[nt][2] * scB;
            stage[(q + 8) * OSTR + c + 1] = O[nt][3] * scB;
        }
    }
    __syncthreads();

    {
        int c = tid;   // one channel row per thread
        const float* xr = x   + ((size_t)(b * CC + c)) * NN + q0;
        float*       orw = out + ((size_t)(b * CC + c)) * NN + q0;
#pragma unroll 4
        for (int n4 = 0; n4 < 16; n4++) {
            float4 xv = *(const float4*)(xr + n4 * 4);
            float4 o;
            o.x = stage[(n4 * 4 + 0) * OSTR + c] + xv.x;
            o.y = stage[(n4 * 4 + 1) * OSTR + c] + xv.y;
            o.z = stage[(n4 * 4 + 2) * OSTR + c] + xv.z;
            o.w = stage[(n4 * 4 + 3) * OSTR + c] + xv.w;
            *(float4*)(orw + n4 * 4) = o;
        }
    }
}

// ---------------------------------------------------------------------------
extern "C" void kernel_launch(void* const* d_in, const int* in_sizes, int n_in,
                              void* d_out, int out_size)
{
    const float* x     = (const float*)d_in[0];
    const float* wq    = (const float*)d_in[1];
    const float* bq    = (const float*)d_in[2];
    const float* wk    = (const float*)d_in[3];
    const float* bk    = (const float*)d_in[4];
    const float* wv    = (const float*)d_in[5];
    const float* bv    = (const float*)d_in[6];
    const float* gamma = (const float*)d_in[7];
    float* out = (float*)d_out;

    __nv_bfloat16 *qh, *ql, *kh, *kl, *vh, *vl;
    cudaGetSymbolAddress((void**)&qh, g_qh);
    cudaGetSymbolAddress((void**)&ql, g_ql);
    cudaGetSymbolAddress((void**)&kh, g_kh);
    cudaGetSymbolAddress((void**)&kl, g_kl);
    cudaGetSymbolAddress((void**)&vh, g_vh);
    cudaGetSymbolAddress((void**)&vl, g_vl);

    dim3 blk(256);
    proj_qk<<<dim3(NN / 128, NB), blk>>>(wq, bq, x, qh, ql);
    proj_qk<<<dim3(NN / 128, NB), blk>>>(wk, bk, x, kh, kl);
    proj_v <<<dim3(NN / 128, NB, CC / 32), blk>>>(wv, bv, x, vh, vl);

    cudaFuncSetAttribute(flash_mma, cudaFuncAttributeMaxDynamicSharedMemorySize, SMEM_BYTES);
    flash_mma<<<dim3(NN / BQ, NB), blk, SMEM_BYTES>>>(x, gamma, out);
}